// round 2
// baseline (speedup 1.0000x reference)
#include <cuda_runtime.h>

#define BB 2
#define CC 512
#define LL 2304
#define NH 8
#define HD 64

// Scratch (allocation-free rule: __device__ globals)
__device__ float g_q[(size_t)BB*NH*LL*HD];
__device__ float g_k[(size_t)BB*NH*LL*HD];
__device__ float g_v[(size_t)BB*NH*LL*HD];
__device__ float g_att[(size_t)BB*CC*LL];
__device__ float g_y[(size_t)BB*CC*LL];

// ---------------------------------------------------------------------------
// QKV GEMM: out[b,h,l,d] = sum_c (x[b,c,l]+pos[c,l]) * W[h*64+d, c] + bias
// Tiles: BM=64 (l), BN=64 (= one head), BK=16. 256 threads, 4x4 per thread.
// ---------------------------------------------------------------------------
__global__ __launch_bounds__(256) void gemm_qkv_kernel(
    const float* __restrict__ x, const float* __restrict__ pos,
    const float* __restrict__ W, const float* __restrict__ bias, int sel)
{
    float* __restrict__ out = (sel == 0) ? g_q : (sel == 1) ? g_k : g_v;
    const int b  = blockIdx.z;
    const int h  = blockIdx.y;
    const int l0 = blockIdx.x * 64;
    const int oc0 = h * 64;

    __shared__ float Xs[16][64];
    __shared__ float Ws[16][68];

    const int tid = threadIdx.x;
    const int tx = tid & 15;
    const int ty = tid >> 4;

    float acc[4][4] = {};
    const float* xb = x + (size_t)b * CC * LL;

    for (int kt = 0; kt < CC; kt += 16) {
        {
            int e = tid * 4;
            int kk = e >> 6, mm = e & 63;
            float4 xv = *(const float4*)(xb  + (size_t)(kt + kk) * LL + l0 + mm);
            float4 pv = *(const float4*)(pos + (size_t)(kt + kk) * LL + l0 + mm);
            *(float4*)&Xs[kk][mm] = make_float4(xv.x+pv.x, xv.y+pv.y, xv.z+pv.z, xv.w+pv.w);
        }
        {
            int nn = tid >> 2, k4 = (tid & 3) * 4;
            float4 wv = *(const float4*)(W + (size_t)(oc0 + nn) * CC + kt + k4);
            Ws[k4+0][nn] = wv.x; Ws[k4+1][nn] = wv.y;
            Ws[k4+2][nn] = wv.z; Ws[k4+3][nn] = wv.w;
        }
        __syncthreads();
        #pragma unroll
        for (int kk = 0; kk < 16; kk++) {
            float4 a = *(const float4*)&Xs[kk][ty*4];
            float4 w = *(const float4*)&Ws[kk][tx*4];
            acc[0][0] += a.x*w.x; acc[0][1] += a.x*w.y; acc[0][2] += a.x*w.z; acc[0][3] += a.x*w.w;
            acc[1][0] += a.y*w.x; acc[1][1] += a.y*w.y; acc[1][2] += a.y*w.z; acc[1][3] += a.y*w.w;
            acc[2][0] += a.z*w.x; acc[2][1] += a.z*w.y; acc[2][2] += a.z*w.z; acc[2][3] += a.z*w.w;
            acc[3][0] += a.w*w.x; acc[3][1] += a.w*w.y; acc[3][2] += a.w*w.z; acc[3][3] += a.w*w.w;
        }
        __syncthreads();
    }
    float4 bv = *(const float4*)(bias + oc0 + tx*4);
    #pragma unroll
    for (int i = 0; i < 4; i++) {
        int l = l0 + ty*4 + i;
        float4 r = make_float4(acc[i][0]+bv.x, acc[i][1]+bv.y, acc[i][2]+bv.z, acc[i][3]+bv.w);
        *(float4*)(out + ((size_t)(b*NH + h) * LL + l) * HD + tx*4) = r;
    }
}

// ---------------------------------------------------------------------------
// Flash attention: 1 thread = 1 query row. K/V tiles (64x64 f32) in SMEM.
// Online softmax with 16-key chunks to bound register pressure.
// Mask is int32 (bool promoted by harness).
// Writes attention output in (B, C, L) channel-major layout for the proj GEMM.
// ---------------------------------------------------------------------------
__global__ __launch_bounds__(128) void attn_kernel(
    const int* __restrict__ mask, const float* __restrict__ rel)
{
    const int b = blockIdx.z, h = blockIdx.y;
    const int l = blockIdx.x * 128 + threadIdx.x;

    __shared__ float Ks[64*64];
    __shared__ float Vs[64*64];
    __shared__ float srel[65];
    if (threadIdx.x < 65) srel[threadIdx.x] = rel[h*65 + threadIdx.x];

    const size_t bh = (size_t)(b * NH + h) * LL;

    float qr[64], o[64];
    {
        const float4* qp = (const float4*)(g_q + (bh + l) * HD);
        #pragma unroll
        for (int i = 0; i < 16; i++) {
            float4 t = qp[i];
            qr[4*i] = t.x; qr[4*i+1] = t.y; qr[4*i+2] = t.z; qr[4*i+3] = t.w;
        }
    }
    #pragma unroll
    for (int d = 0; d < 64; d++) o[d] = 0.f;
    float mrow = -1e30f, lsum = 0.f;

    const int4* mrowp = (const int4*)(mask + ((size_t)h * LL + l) * LL);

    const int jrow = threadIdx.x >> 1;
    const int half = (threadIdx.x & 1) * 32;

    for (int kt = 0; kt < LL; kt += 64) {
        // cooperative K/V tile load (coalesced float4)
        const float4* kp = (const float4*)(g_k + (bh + kt + jrow) * HD + half);
        const float4* vp = (const float4*)(g_v + (bh + kt + jrow) * HD + half);
        float4* kd = (float4*)&Ks[jrow*64 + half];
        float4* vd = (float4*)&Vs[jrow*64 + half];
        #pragma unroll
        for (int i = 0; i < 8; i++) { kd[i] = kp[i]; vd[i] = vp[i]; }
        __syncthreads();

        #pragma unroll 1
        for (int c = 0; c < 4; c++) {
            const int k0 = kt + c * 16;
            int mvals[16];
            {
                const int4* mp = mrowp + (k0 >> 2);
                #pragma unroll
                for (int w = 0; w < 4; w++) {
                    int4 mw = mp[w];
                    mvals[w*4+0] = mw.x; mvals[w*4+1] = mw.y;
                    mvals[w*4+2] = mw.z; mvals[w*4+3] = mw.w;
                }
            }

            float s[16];
            #pragma unroll
            for (int j = 0; j < 16; j++) {
                const float4* kk = (const float4*)&Ks[(c*16 + j) * 64];
                float acc = 0.f;
                #pragma unroll
                for (int dd = 0; dd < 16; dd++) {
                    float4 kv = kk[dd];
                    acc += qr[4*dd]*kv.x + qr[4*dd+1]*kv.y
                         + qr[4*dd+2]*kv.z + qr[4*dd+3]*kv.w;
                }
                int diff = l - (k0 + j);
                diff = max(-32, min(32, diff));
                s[j] = mvals[j] ? acc * 0.125f + srel[diff + 32] : -1e9f;
            }
            float tm = s[0];
            #pragma unroll
            for (int j = 1; j < 16; j++) tm = fmaxf(tm, s[j]);
            float mnew = fmaxf(mrow, tm);
            float corr = __expf(mrow - mnew);
            lsum *= corr;
            #pragma unroll
            for (int d = 0; d < 64; d++) o[d] *= corr;
            #pragma unroll
            for (int j = 0; j < 16; j++) {
                float p = __expf(s[j] - mnew);
                lsum += p;
                const float4* vv = (const float4*)&Vs[(c*16 + j) * 64];
                #pragma unroll
                for (int dd = 0; dd < 16; dd++) {
                    float4 t = vv[dd];
                    o[4*dd]   += p*t.x; o[4*dd+1] += p*t.y;
                    o[4*dd+2] += p*t.z; o[4*dd+3] += p*t.w;
                }
            }
            mrow = mnew;
        }
        __syncthreads();
    }
    const float inv = 1.f / lsum;
    float* ob = g_att + (size_t)b * CC * LL + (size_t)h * HD * LL + l;
    #pragma unroll
    for (int d = 0; d < 64; d++) ob[(size_t)d * LL] = o[d] * inv;   // coalesced over l
}

// ---------------------------------------------------------------------------
// Output projection + residual: y[b,o,l] = sum_c Wo[o,c]*att[b,c,l] + bo + x
// ---------------------------------------------------------------------------
__global__ __launch_bounds__(256) void gemm_proj_kernel(
    const float* __restrict__ W, const float* __restrict__ bias,
    const float* __restrict__ xres)
{
    const int b = blockIdx.z;
    const int oc0 = blockIdx.y * 64;
    const int l0  = blockIdx.x * 64;

    __shared__ float Xs[16][64];
    __shared__ float Ws[16][68];

    const int tid = threadIdx.x;
    const int tx = tid & 15, ty = tid >> 4;
    float acc[4][4] = {};
    const float* ab = g_att + (size_t)b * CC * LL;

    for (int kt = 0; kt < CC; kt += 16) {
        {
            int e = tid * 4;
            int kk = e >> 6, mm = e & 63;
            *(float4*)&Xs[kk][mm] = *(const float4*)(ab + (size_t)(kt+kk)*LL + l0 + mm);
        }
        {
            int nn = tid >> 2, k4 = (tid & 3) * 4;
            float4 wv = *(const float4*)(W + (size_t)(oc0+nn)*CC + kt + k4);
            Ws[k4+0][nn]=wv.x; Ws[k4+1][nn]=wv.y; Ws[k4+2][nn]=wv.z; Ws[k4+3][nn]=wv.w;
        }
        __syncthreads();
        #pragma unroll
        for (int kk = 0; kk < 16; kk++) {
            float4 a = *(const float4*)&Xs[kk][ty*4];
            float4 w = *(const float4*)&Ws[kk][tx*4];
            acc[0][0] += a.x*w.x; acc[0][1] += a.x*w.y; acc[0][2] += a.x*w.z; acc[0][3] += a.x*w.w;
            acc[1][0] += a.y*w.x; acc[1][1] += a.y*w.y; acc[1][2] += a.y*w.z; acc[1][3] += a.y*w.w;
            acc[2][0] += a.z*w.x; acc[2][1] += a.z*w.y; acc[2][2] += a.z*w.z; acc[2][3] += a.z*w.w;
            acc[3][0] += a.w*w.x; acc[3][1] += a.w*w.y; acc[3][2] += a.w*w.z; acc[3][3] += a.w*w.w;
        }
        __syncthreads();
    }
    #pragma unroll
    for (int j = 0; j < 4; j++) {
        int oc = oc0 + tx*4 + j;
        float bv = bias[oc];
        size_t base = (size_t)b*CC*LL + (size_t)oc*LL + l0 + ty*4;
        float4 xr = *(const float4*)(xres + base);
        float4 r = make_float4(acc[0][j]+bv+xr.x, acc[1][j]+bv+xr.y,
                               acc[2][j]+bv+xr.z, acc[3][j]+bv+xr.w);
        *(float4*)(g_y + base) = r;
    }
}

// ---------------------------------------------------------------------------
// LayerNorm over channels (C=512) per pixel. One warp per pixel, two-pass
// (values held in registers), exact mean/var like jnp.var.
// ---------------------------------------------------------------------------
__global__ __launch_bounds__(256) void ln_kernel(
    const float* __restrict__ gamma, const float* __restrict__ beta,
    float* __restrict__ out)
{
    const int warp = threadIdx.x >> 5, lane = threadIdx.x & 31;
    const int p = blockIdx.x * 8 + warp;           // 0 .. B*LL-1 (grid exact)
    const int b = p / LL, l = p % LL;
    const float* yb = g_y + (size_t)b * CC * LL + l;

    float vals[16];
    float sum = 0.f;
    #pragma unroll
    for (int i = 0; i < 16; i++) { vals[i] = yb[(size_t)(lane + 32*i) * LL]; sum += vals[i]; }
    #pragma unroll
    for (int off = 16; off > 0; off >>= 1) sum += __shfl_xor_sync(0xffffffffu, sum, off);
    float mean = sum * (1.f/CC);
    float vs = 0.f;
    #pragma unroll
    for (int i = 0; i < 16; i++) { float d = vals[i]-mean; vs += d*d; }
    #pragma unroll
    for (int off = 16; off > 0; off >>= 1) vs += __shfl_xor_sync(0xffffffffu, vs, off);
    float rs = rsqrtf(vs * (1.f/CC) + 1e-5f);

    float* ob = out + (size_t)b * CC * LL + l;
    #pragma unroll
    for (int i = 0; i < 16; i++) {
        int c = lane + 32*i;
        ob[(size_t)c * LL] = (vals[i]-mean)*rs*gamma[c] + beta[c];
    }
}

// ---------------------------------------------------------------------------
extern "C" void kernel_launch(void* const* d_in, const int* in_sizes, int n_in,
                              void* d_out, int out_size)
{
    const float* x           = (const float*)d_in[0];
    const int*   mask        = (const int*)d_in[1];
    const float* pos         = (const float*)d_in[2];
    const float* Wq  = (const float*)d_in[3];
    const float* bq  = (const float*)d_in[4];
    const float* Wk  = (const float*)d_in[5];
    const float* bk  = (const float*)d_in[6];
    const float* Wv  = (const float*)d_in[7];
    const float* bv  = (const float*)d_in[8];
    const float* Wo  = (const float*)d_in[9];
    const float* bo  = (const float*)d_in[10];
    const float* rel = (const float*)d_in[11];
    const float* gam = (const float*)d_in[12];
    const float* bet = (const float*)d_in[13];
    float* out = (float*)d_out;

    dim3 gg(LL/64, NH, BB);
    gemm_qkv_kernel<<<gg, 256>>>(x, pos, Wq, bq, 0);
    gemm_qkv_kernel<<<gg, 256>>>(x, pos, Wk, bk, 1);
    gemm_qkv_kernel<<<gg, 256>>>(x, pos, Wv, bv, 2);
    attn_kernel<<<dim3(LL/128, NH, BB), 128>>>(mask, rel);
    gemm_proj_kernel<<<gg, 256>>>(Wo, bo, x);
    ln_kernel<<<(BB*LL)/8, 256>>>(gam, bet, out);
}

// round 5
// speedup vs baseline: 2.7171x; 2.7171x over previous
#include <cuda_runtime.h>
#include <cstdint>

#define BB 2
#define CC 512
#define LL 2304
#define NH 8
#define HD 64
#define KT 64
#define NT (LL/KT)        // 36
#define MW 72             // mask words per row (2304/32)

// ---------------- scratch (__device__ globals; no allocs allowed) ----------
__device__ float    g_q[(size_t)BB*NH*LL*HD];
__device__ float    g_k[(size_t)BB*NH*LL*HD];
__device__ float    g_v[(size_t)BB*NH*LL*HD];
__device__ float    g_att[(size_t)BB*CC*LL];
__device__ float    g_y[(size_t)BB*CC*LL];
__device__ unsigned g_mbits[(size_t)NH*LL*MW];

// ---------------- helpers ---------------------------------------------------
__device__ __forceinline__ uint32_t smem_u32(const void* p) {
    uint32_t a;
    asm("{ .reg .u64 t; cvta.to.shared.u64 t, %1; cvt.u32.u64 %0, t; }" : "=r"(a) : "l"(p));
    return a;
}
__device__ __forceinline__ uint32_t tf32b(float x) {
    uint32_t u; asm("cvt.rna.tf32.f32 %0, %1;" : "=r"(u) : "f"(x));
    return u;
}
__device__ __forceinline__ void mma8(float* c, const uint32_t* a, uint32_t b0, uint32_t b1) {
    asm volatile("mma.sync.aligned.m16n8k8.row.col.f32.tf32.tf32.f32 "
        "{%0,%1,%2,%3}, {%4,%5,%6,%7}, {%8,%9}, {%0,%1,%2,%3};"
        : "+f"(c[0]), "+f"(c[1]), "+f"(c[2]), "+f"(c[3])
        : "r"(a[0]), "r"(a[1]), "r"(a[2]), "r"(a[3]), "r"(b0), "r"(b1));
}
#define CP_ASYNC(dst, src) asm volatile("cp.async.cg.shared.global [%0], [%1], 16;" :: "r"(dst), "l"(src))
#define CP_COMMIT()        asm volatile("cp.async.commit_group;" ::: "memory")
#define CP_WAIT0()         asm volatile("cp.async.wait_group 0;" ::: "memory")

// SMEM float offsets
#define OFF_Q   0                 // 256 x 68
#define OFF_K   17408             // 2 x 64 x 68
#define OFF_V   26112             // 2 x 64 x 68
#define OFF_P   34816             // 8 warps x 32 x 68
#define OFF_REL 52224             // 68
#define SM_FLOATS 52292
#define SM_BYTES (SM_FLOATS*4)

// ---------------------------------------------------------------------------
// Mask bitpack: one thread packs 32 int32 -> 1 word
// ---------------------------------------------------------------------------
__global__ __launch_bounds__(256) void pack_kernel(const int* __restrict__ mask)
{
    size_t idx = (size_t)blockIdx.x * 256 + threadIdx.x;   // word index
    const int4* src = (const int4*)(mask + idx * 32);
    unsigned bits = 0;
    #pragma unroll
    for (int i = 0; i < 8; i++) {
        int4 v = src[i];
        bits |= (v.x ? 1u : 0u) << (i*4 + 0);
        bits |= (v.y ? 1u : 0u) << (i*4 + 1);
        bits |= (v.z ? 1u : 0u) << (i*4 + 2);
        bits |= (v.w ? 1u : 0u) << (i*4 + 3);
    }
    g_mbits[idx] = bits;
}

// ---------------------------------------------------------------------------
// tf32 mma.sync flash attention. 256 threads = 8 warps, 32 queries/warp.
// ---------------------------------------------------------------------------
__global__ __launch_bounds__(256) void attn_kernel(const float* __restrict__ rel)
{
    extern __shared__ float sm[];
    const int tid = threadIdx.x, wid = tid >> 5, lane = tid & 31;
    const int lr = lane >> 2, lc = lane & 3;   // fragment row/col ids
    const int b = blockIdx.z, h = blockIdx.y;
    const int q0 = blockIdx.x * 256;
    const int wq = wid * 32;
    const size_t bh = (size_t)(b * NH + h) * LL;

    float* Qs = sm + OFF_Q;
    float* Pw = sm + OFF_P + wid * (32 * 68);
    float* srel = sm + OFF_REL;

    if (tid < 65) srel[tid] = rel[h * 65 + tid];

    // Q tile -> SMEM (fp32, padded stride 68)
    {
        const float4* qp = (const float4*)(g_q + (bh + q0) * HD);
        #pragma unroll
        for (int i = 0; i < 16; i++) {
            int fidx = i * 256 + tid;             // 0..4095 float4s (256 rows)
            int row = fidx >> 4, c4 = (fidx & 15) * 4;
            float4 v = qp[fidx];
            float* d = Qs + row * 68 + c4;
            d[0] = v.x; d[1] = v.y; d[2] = v.z; d[3] = v.w;
        }
    }

    // prefetch tile 0 (64 rows = 1024 float4s)
    {
        const float* gk = g_k + bh * HD;
        const float* gv = g_v + bh * HD;
        uint32_t sk = smem_u32(sm + OFF_K), sv = smem_u32(sm + OFF_V);
        #pragma unroll
        for (int i = 0; i < 4; i++) {
            int fidx = i * 256 + tid;             // 0..1023
            int row = fidx >> 4, c4 = (fidx & 15) * 4;
            uint32_t off = (uint32_t)(row * 68 + c4) * 4;
            CP_ASYNC(sk + off, gk + row * HD + c4);
            CP_ASYNC(sv + off, gv + row * HD + c4);
        }
        CP_COMMIT();
    }

    float oacc[2][8][4] = {};
    float lsum4[4] = {};
    const float rel0c = rel[h * 65 + 0], rel64c = rel[h * 65 + 64];

    for (int t = 0; t < NT; t++) {
        const int kt = t * KT;
        const int buf = t & 1;
        float* Ks = sm + OFF_K + buf * (64 * 68);
        float* Vs = sm + OFF_V + buf * (64 * 68);

        CP_WAIT0();
        __syncthreads();

        if (t + 1 < NT) {
            const float* gk = g_k + (bh + kt + KT) * HD;
            const float* gv = g_v + (bh + kt + KT) * HD;
            uint32_t sk = smem_u32(sm + OFF_K + (buf ^ 1) * (64 * 68));
            uint32_t sv = smem_u32(sm + OFF_V + (buf ^ 1) * (64 * 68));
            #pragma unroll
            for (int i = 0; i < 4; i++) {
                int fidx = i * 256 + tid;         // 0..1023
                int row = fidx >> 4, c4 = (fidx & 15) * 4;
                uint32_t off = (uint32_t)(row * 68 + c4) * 4;
                CP_ASYNC(sk + off, gk + row * HD + c4);
                CP_ASYNC(sv + off, gv + row * HD + c4);
            }
            CP_COMMIT();
        }

        // mask words for this thread's 4 rows
        uint2 mwv[4];
        #pragma unroll
        for (int rr = 0; rr < 4; rr++) {
            int l = q0 + wq + (rr >> 1) * 16 + (rr & 1) * 8 + lr;
            mwv[rr] = *(const uint2*)(g_mbits + ((size_t)h * LL + l) * MW + 2 * t);
        }

        // ---- QK ----
        float sacc[2][8][4] = {};
        #pragma unroll
        for (int ks = 0; ks < 8; ks++) {
            uint32_t af[2][4];
            #pragma unroll
            for (int mt = 0; mt < 2; mt++) {
                const float* qb = Qs + (wq + mt * 16 + lr) * 68 + ks * 8 + lc;
                af[mt][0] = tf32b(qb[0]);
                af[mt][1] = tf32b(qb[8 * 68]);
                af[mt][2] = tf32b(qb[4]);
                af[mt][3] = tf32b(qb[8 * 68 + 4]);
            }
            #pragma unroll
            for (int j = 0; j < 8; j++) {
                const float* kb = Ks + (8 * j + lr) * 68 + ks * 8 + lc;
                uint32_t b0 = tf32b(kb[0]);
                uint32_t b1 = tf32b(kb[4]);
                mma8(sacc[0][j], af[0], b0, b1);
                mma8(sacc[1][j], af[1], b0, b1);
            }
        }

        // ---- softmax epilogue -> P (tf32 bits) in per-warp SMEM ----
        #pragma unroll
        for (int mt = 0; mt < 2; mt++) {
            #pragma unroll
            for (int rh = 0; rh < 2; rh++) {
                const int rowloc = mt * 16 + rh * 8 + lr;
                const int l = q0 + wq + rowloc;
                const uint2 mw = mwv[mt * 2 + rh];
                const bool hi = (l - kt) >= 96;
                const bool lo = (kt - l) >= 33;
                float rsum = 0.f;
                #pragma unroll
                for (int j = 0; j < 8; j++) {
                    const int k0 = 8 * j + 2 * lc;
                    float v0 = sacc[mt][j][rh * 2 + 0];
                    float v1 = sacc[mt][j][rh * 2 + 1];
                    float b0v, b1v;
                    if (hi)      { b0v = rel64c; b1v = rel64c; }
                    else if (lo) { b0v = rel0c;  b1v = rel0c;  }
                    else {
                        int e = l - kt - k0 + 32;
                        int e0 = e < 0 ? 0 : (e > 64 ? 64 : e);
                        int e1 = e - 1; e1 = e1 < 0 ? 0 : (e1 > 64 ? 64 : e1);
                        b0v = srel[e0]; b1v = srel[e1];
                    }
                    unsigned mword = (j < 4) ? mw.x : mw.y;
                    float p0 = ((mword >> (k0 & 31)) & 1u)       ? __expf(fmaf(v0, 0.125f, b0v)) : 0.f;
                    float p1 = ((mword >> ((k0 + 1) & 31)) & 1u) ? __expf(fmaf(v1, 0.125f, b1v)) : 0.f;
                    rsum += p0 + p1;
                    uint2 pp; pp.x = tf32b(p0); pp.y = tf32b(p1);
                    *(uint2*)(Pw + rowloc * 68 + k0) = pp;
                }
                rsum += __shfl_xor_sync(0xffffffffu, rsum, 1);
                rsum += __shfl_xor_sync(0xffffffffu, rsum, 2);
                lsum4[mt * 2 + rh] += rsum;
            }
        }
        __syncwarp();

        // ---- PV ----
        #pragma unroll
        for (int ks = 0; ks < 8; ks++) {
            uint32_t af[2][4];
            #pragma unroll
            for (int mt = 0; mt < 2; mt++) {
                const uint32_t* pb = (const uint32_t*)(Pw + (mt * 16 + lr) * 68 + ks * 8 + lc);
                af[mt][0] = pb[0];
                af[mt][1] = pb[8 * 68];
                af[mt][2] = pb[4];
                af[mt][3] = pb[8 * 68 + 4];
            }
            #pragma unroll
            for (int j = 0; j < 8; j++) {
                const float* vb = Vs + (ks * 8 + lc) * 68 + 8 * j + lr;
                uint32_t b0 = tf32b(vb[0]);
                uint32_t b1 = tf32b(vb[4 * 68]);
                mma8(oacc[0][j], af[0], b0, b1);
                mma8(oacc[1][j], af[1], b0, b1);
            }
        }
        __syncwarp();
    }

    // ---- finalize: O/lsum -> Pw (fp32) -> coalesced gmem store ----
    #pragma unroll
    for (int mt = 0; mt < 2; mt++) {
        #pragma unroll
        for (int rh = 0; rh < 2; rh++) {
            const int rowloc = mt * 16 + rh * 8 + lr;
            const float inv = 1.f / lsum4[mt * 2 + rh];
            #pragma unroll
            for (int j = 0; j < 8; j++) {
                float2 o;
                o.x = oacc[mt][j][rh * 2 + 0] * inv;
                o.y = oacc[mt][j][rh * 2 + 1] * inv;
                *(float2*)(Pw + rowloc * 68 + 8 * j + 2 * lc) = o;
            }
        }
    }
    __syncwarp();
    {
        const int l = q0 + wq + lane;
        float* ob = g_att + ((size_t)b * CC + h * 64) * LL + l;
        #pragma unroll
        for (int dd = 0; dd < 64; dd++)
            ob[(size_t)dd * LL] = Pw[lane * 68 + dd];
    }
}

// ---------------------------------------------------------------------------
// QKV GEMM (FFMA, exact fp32): out[b,h,l,d] = sum_c (x+pos)*W + bias
// ---------------------------------------------------------------------------
__global__ __launch_bounds__(256) void gemm_qkv_kernel(
    const float* __restrict__ x, const float* __restrict__ pos,
    const float* __restrict__ W, const float* __restrict__ bias, int sel)
{
    float* __restrict__ out = (sel == 0) ? g_q : (sel == 1) ? g_k : g_v;
    const int b = blockIdx.z, h = blockIdx.y;
    const int l0 = blockIdx.x * 64;
    const int oc0 = h * 64;

    __shared__ float Xs[16][64];
    __shared__ float Ws[16][68];

    const int tid = threadIdx.x;
    const int tx = tid & 15, ty = tid >> 4;

    float acc[4][4] = {};
    const float* xb = x + (size_t)b * CC * LL;

    for (int kt = 0; kt < CC; kt += 16) {
        {
            int e = tid * 4;
            int kk = e >> 6, mm = e & 63;
            float4 xv = *(const float4*)(xb  + (size_t)(kt + kk) * LL + l0 + mm);
            float4 pv = *(const float4*)(pos + (size_t)(kt + kk) * LL + l0 + mm);
            *(float4*)&Xs[kk][mm] = make_float4(xv.x + pv.x, xv.y + pv.y, xv.z + pv.z, xv.w + pv.w);
        }
        {
            int nn = tid >> 2, k4 = (tid & 3) * 4;
            float4 wv = *(const float4*)(W + (size_t)(oc0 + nn) * CC + kt + k4);
            Ws[k4+0][nn] = wv.x; Ws[k4+1][nn] = wv.y;
            Ws[k4+2][nn] = wv.z; Ws[k4+3][nn] = wv.w;
        }
        __syncthreads();
        #pragma unroll
        for (int kk = 0; kk < 16; kk++) {
            float4 a = *(const float4*)&Xs[kk][ty * 4];
            float4 w = *(const float4*)&Ws[kk][tx * 4];
            acc[0][0] += a.x*w.x; acc[0][1] += a.x*w.y; acc[0][2] += a.x*w.z; acc[0][3] += a.x*w.w;
            acc[1][0] += a.y*w.x; acc[1][1] += a.y*w.y; acc[1][2] += a.y*w.z; acc[1][3] += a.y*w.w;
            acc[2][0] += a.z*w.x; acc[2][1] += a.z*w.y; acc[2][2] += a.z*w.z; acc[2][3] += a.z*w.w;
            acc[3][0] += a.w*w.x; acc[3][1] += a.w*w.y; acc[3][2] += a.w*w.z; acc[3][3] += a.w*w.w;
        }
        __syncthreads();
    }
    float4 bv = *(const float4*)(bias + oc0 + tx * 4);
    #pragma unroll
    for (int i = 0; i < 4; i++) {
        int l = l0 + ty * 4 + i;
        float4 r = make_float4(acc[i][0] + bv.x, acc[i][1] + bv.y, acc[i][2] + bv.z, acc[i][3] + bv.w);
        *(float4*)(out + ((size_t)(b * NH + h) * LL + l) * HD + tx * 4) = r;
    }
}

// ---------------------------------------------------------------------------
// Output projection + residual (FFMA)
// ---------------------------------------------------------------------------
__global__ __launch_bounds__(256) void gemm_proj_kernel(
    const float* __restrict__ W, const float* __restrict__ bias,
    const float* __restrict__ xres)
{
    const int b = blockIdx.z;
    const int oc0 = blockIdx.y * 64;
    const int l0  = blockIdx.x * 64;

    __shared__ float Xs[16][64];
    __shared__ float Ws[16][68];

    const int tid = threadIdx.x;
    const int tx = tid & 15, ty = tid >> 4;
    float acc[4][4] = {};
    const float* ab = g_att + (size_t)b * CC * LL;

    for (int kt = 0; kt < CC; kt += 16) {
        {
            int e = tid * 4;
            int kk = e >> 6, mm = e & 63;
            *(float4*)&Xs[kk][mm] = *(const float4*)(ab + (size_t)(kt + kk) * LL + l0 + mm);
        }
        {
            int nn = tid >> 2, k4 = (tid & 3) * 4;
            float4 wv = *(const float4*)(W + (size_t)(oc0 + nn) * CC + kt + k4);
            Ws[k4+0][nn] = wv.x; Ws[k4+1][nn] = wv.y; Ws[k4+2][nn] = wv.z; Ws[k4+3][nn] = wv.w;
        }
        __syncthreads();
        #pragma unroll
        for (int kk = 0; kk < 16; kk++) {
            float4 a = *(const float4*)&Xs[kk][ty * 4];
            float4 w = *(const float4*)&Ws[kk][tx * 4];
            acc[0][0] += a.x*w.x; acc[0][1] += a.x*w.y; acc[0][2] += a.x*w.z; acc[0][3] += a.x*w.w;
            acc[1][0] += a.y*w.x; acc[1][1] += a.y*w.y; acc[1][2] += a.y*w.z; acc[1][3] += a.y*w.w;
            acc[2][0] += a.z*w.x; acc[2][1] += a.z*w.y; acc[2][2] += a.z*w.z; acc[2][3] += a.z*w.w;
            acc[3][0] += a.w*w.x; acc[3][1] += a.w*w.y; acc[3][2] += a.w*w.z; acc[3][3] += a.w*w.w;
        }
        __syncthreads();
    }
    #pragma unroll
    for (int j = 0; j < 4; j++) {
        int oc = oc0 + tx * 4 + j;
        float bvs = bias[oc];
        size_t base = (size_t)b * CC * LL + (size_t)oc * LL + l0 + ty * 4;
        float4 xr = *(const float4*)(xres + base);
        float4 r = make_float4(acc[0][j] + bvs + xr.x, acc[1][j] + bvs + xr.y,
                               acc[2][j] + bvs + xr.z, acc[3][j] + bvs + xr.w);
        *(float4*)(g_y + base) = r;
    }
}

// ---------------------------------------------------------------------------
// LayerNorm over channels, one warp per pixel
// ---------------------------------------------------------------------------
__global__ __launch_bounds__(256) void ln_kernel(
    const float* __restrict__ gamma, const float* __restrict__ beta,
    float* __restrict__ out)
{
    const int warp = threadIdx.x >> 5, lane = threadIdx.x & 31;
    const int p = blockIdx.x * 8 + warp;
    const int b = p / LL, l = p % LL;
    const float* yb = g_y + (size_t)b * CC * LL + l;

    float vals[16];
    float sum = 0.f;
    #pragma unroll
    for (int i = 0; i < 16; i++) { vals[i] = yb[(size_t)(lane + 32 * i) * LL]; sum += vals[i]; }
    #pragma unroll
    for (int off = 16; off > 0; off >>= 1) sum += __shfl_xor_sync(0xffffffffu, sum, off);
    float mean = sum * (1.f / CC);
    float vs = 0.f;
    #pragma unroll
    for (int i = 0; i < 16; i++) { float d = vals[i] - mean; vs += d * d; }
    #pragma unroll
    for (int off = 16; off > 0; off >>= 1) vs += __shfl_xor_sync(0xffffffffu, vs, off);
    float rs = rsqrtf(vs * (1.f / CC) + 1e-5f);

    float* ob = out + (size_t)b * CC * LL + l;
    #pragma unroll
    for (int i = 0; i < 16; i++) {
        int c = lane + 32 * i;
        ob[(size_t)c * LL] = (vals[i] - mean) * rs * gamma[c] + beta[c];
    }
}

// ---------------------------------------------------------------------------
extern "C" void kernel_launch(void* const* d_in, const int* in_sizes, int n_in,
                              void* d_out, int out_size)
{
    const float* x    = (const float*)d_in[0];
    const int*   mask = (const int*)d_in[1];
    const float* pos  = (const float*)d_in[2];
    const float* Wq = (const float*)d_in[3];
    const float* bq = (const float*)d_in[4];
    const float* Wk = (const float*)d_in[5];
    const float* bk = (const float*)d_in[6];
    const float* Wv = (const float*)d_in[7];
    const float* bv = (const float*)d_in[8];
    const float* Wo = (const float*)d_in[9];
    const float* bo = (const float*)d_in[10];
    const float* rel = (const float*)d_in[11];
    const float* gam = (const float*)d_in[12];
    const float* bet = (const float*)d_in[13];
    float* out = (float*)d_out;

    static bool attr_set = false;
    if (!attr_set) {
        cudaFuncSetAttribute(attn_kernel, cudaFuncAttributeMaxDynamicSharedMemorySize, SM_BYTES);
        attr_set = true;
    }

    dim3 gg(LL / 64, NH, BB);
    gemm_qkv_kernel<<<gg, 256>>>(x, pos, Wq, bq, 0);
    gemm_qkv_kernel<<<gg, 256>>>(x, pos, Wk, bk, 1);
    gemm_qkv_kernel<<<gg, 256>>>(x, pos, Wv, bv, 2);
    pack_kernel<<<(NH * LL * MW) / 256, 256>>>(mask);
    attn_kernel<<<dim3(LL / 256, NH, BB), 256, SM_BYTES>>>(rel);
    gemm_proj_kernel<<<gg, 256>>>(Wo, bo, x);
    ln_kernel<<<(BB * LL) / 8, 256>>>(gam, bet, out);
}

// round 6
// speedup vs baseline: 3.4483x; 1.2691x over previous
#include <cuda_runtime.h>
#include <cstdint>

#define BB 2
#define CC 512
#define LL 2304
#define NH 8
#define HD 64
#define KT 64
#define NT (LL/KT)        // 36
#define MW 72             // mask words per row (2304/32)

// ---------------- scratch (__device__ globals; no allocs allowed) ----------
__device__ float    g_q[(size_t)BB*NH*LL*HD];
__device__ float    g_k[(size_t)BB*NH*LL*HD];
__device__ float    g_v[(size_t)BB*NH*LL*HD];
__device__ float    g_att[(size_t)BB*CC*LL];
__device__ float    g_y[(size_t)BB*CC*LL];
__device__ unsigned g_mbits[(size_t)NH*LL*MW];

// ---------------- helpers ---------------------------------------------------
__device__ __forceinline__ uint32_t smem_u32(const void* p) {
    uint32_t a;
    asm("{ .reg .u64 t; cvta.to.shared.u64 t, %1; cvt.u32.u64 %0, t; }" : "=r"(a) : "l"(p));
    return a;
}
__device__ __forceinline__ uint32_t tf32b(float x) {
    uint32_t u; asm("cvt.rna.tf32.f32 %0, %1;" : "=r"(u) : "f"(x));
    return u;
}
__device__ __forceinline__ void mma8(float* c, const uint32_t* a, uint32_t b0, uint32_t b1) {
    asm volatile("mma.sync.aligned.m16n8k8.row.col.f32.tf32.tf32.f32 "
        "{%0,%1,%2,%3}, {%4,%5,%6,%7}, {%8,%9}, {%0,%1,%2,%3};"
        : "+f"(c[0]), "+f"(c[1]), "+f"(c[2]), "+f"(c[3])
        : "r"(a[0]), "r"(a[1]), "r"(a[2]), "r"(a[3]), "r"(b0), "r"(b1));
}
#define CP_ASYNC(dst, src) asm volatile("cp.async.cg.shared.global [%0], [%1], 16;" :: "r"(dst), "l"(src))
#define CP_COMMIT()        asm volatile("cp.async.commit_group;" ::: "memory")
#define CP_WAIT0()         asm volatile("cp.async.wait_group 0;" ::: "memory")

// ======================= attention kernel (unchanged) =======================
#define OFF_Q   0                 // 256 x 68
#define OFF_K   17408             // 2 x 64 x 68
#define OFF_V   26112             // 2 x 64 x 68
#define OFF_P   34816             // 8 warps x 32 x 68
#define OFF_REL 52224             // 68
#define SM_FLOATS 52292
#define SM_BYTES (SM_FLOATS*4)

__global__ __launch_bounds__(256) void pack_kernel(const int* __restrict__ mask)
{
    size_t idx = (size_t)blockIdx.x * 256 + threadIdx.x;   // word index
    const int4* src = (const int4*)(mask + idx * 32);
    unsigned bits = 0;
    #pragma unroll
    for (int i = 0; i < 8; i++) {
        int4 v = src[i];
        bits |= (v.x ? 1u : 0u) << (i*4 + 0);
        bits |= (v.y ? 1u : 0u) << (i*4 + 1);
        bits |= (v.z ? 1u : 0u) << (i*4 + 2);
        bits |= (v.w ? 1u : 0u) << (i*4 + 3);
    }
    g_mbits[idx] = bits;
}

__global__ __launch_bounds__(256) void attn_kernel(const float* __restrict__ rel)
{
    extern __shared__ float sm[];
    const int tid = threadIdx.x, wid = tid >> 5, lane = tid & 31;
    const int lr = lane >> 2, lc = lane & 3;
    const int b = blockIdx.z, h = blockIdx.y;
    const int q0 = blockIdx.x * 256;
    const int wq = wid * 32;
    const size_t bh = (size_t)(b * NH + h) * LL;

    float* Qs = sm + OFF_Q;
    float* Pw = sm + OFF_P + wid * (32 * 68);
    float* srel = sm + OFF_REL;

    if (tid < 65) srel[tid] = rel[h * 65 + tid];

    {
        const float4* qp = (const float4*)(g_q + (bh + q0) * HD);
        #pragma unroll
        for (int i = 0; i < 16; i++) {
            int fidx = i * 256 + tid;
            int row = fidx >> 4, c4 = (fidx & 15) * 4;
            float4 v = qp[fidx];
            float* d = Qs + row * 68 + c4;
            d[0] = v.x; d[1] = v.y; d[2] = v.z; d[3] = v.w;
        }
    }

    {
        const float* gk = g_k + bh * HD;
        const float* gv = g_v + bh * HD;
        uint32_t sk = smem_u32(sm + OFF_K), sv = smem_u32(sm + OFF_V);
        #pragma unroll
        for (int i = 0; i < 4; i++) {
            int fidx = i * 256 + tid;
            int row = fidx >> 4, c4 = (fidx & 15) * 4;
            uint32_t off = (uint32_t)(row * 68 + c4) * 4;
            CP_ASYNC(sk + off, gk + row * HD + c4);
            CP_ASYNC(sv + off, gv + row * HD + c4);
        }
        CP_COMMIT();
    }

    float oacc[2][8][4] = {};
    float lsum4[4] = {};
    const float rel0c = rel[h * 65 + 0], rel64c = rel[h * 65 + 64];

    for (int t = 0; t < NT; t++) {
        const int kt = t * KT;
        const int buf = t & 1;
        float* Ks = sm + OFF_K + buf * (64 * 68);
        float* Vs = sm + OFF_V + buf * (64 * 68);

        CP_WAIT0();
        __syncthreads();

        if (t + 1 < NT) {
            const float* gk = g_k + (bh + kt + KT) * HD;
            const float* gv = g_v + (bh + kt + KT) * HD;
            uint32_t sk = smem_u32(sm + OFF_K + (buf ^ 1) * (64 * 68));
            uint32_t sv = smem_u32(sm + OFF_V + (buf ^ 1) * (64 * 68));
            #pragma unroll
            for (int i = 0; i < 4; i++) {
                int fidx = i * 256 + tid;
                int row = fidx >> 4, c4 = (fidx & 15) * 4;
                uint32_t off = (uint32_t)(row * 68 + c4) * 4;
                CP_ASYNC(sk + off, gk + row * HD + c4);
                CP_ASYNC(sv + off, gv + row * HD + c4);
            }
            CP_COMMIT();
        }

        uint2 mwv[4];
        #pragma unroll
        for (int rr = 0; rr < 4; rr++) {
            int l = q0 + wq + (rr >> 1) * 16 + (rr & 1) * 8 + lr;
            mwv[rr] = *(const uint2*)(g_mbits + ((size_t)h * LL + l) * MW + 2 * t);
        }

        float sacc[2][8][4] = {};
        #pragma unroll
        for (int ks = 0; ks < 8; ks++) {
            uint32_t af[2][4];
            #pragma unroll
            for (int mt = 0; mt < 2; mt++) {
                const float* qb = Qs + (wq + mt * 16 + lr) * 68 + ks * 8 + lc;
                af[mt][0] = tf32b(qb[0]);
                af[mt][1] = tf32b(qb[8 * 68]);
                af[mt][2] = tf32b(qb[4]);
                af[mt][3] = tf32b(qb[8 * 68 + 4]);
            }
            #pragma unroll
            for (int j = 0; j < 8; j++) {
                const float* kb = Ks + (8 * j + lr) * 68 + ks * 8 + lc;
                uint32_t b0 = tf32b(kb[0]);
                uint32_t b1 = tf32b(kb[4]);
                mma8(sacc[0][j], af[0], b0, b1);
                mma8(sacc[1][j], af[1], b0, b1);
            }
        }

        #pragma unroll
        for (int mt = 0; mt < 2; mt++) {
            #pragma unroll
            for (int rh = 0; rh < 2; rh++) {
                const int rowloc = mt * 16 + rh * 8 + lr;
                const int l = q0 + wq + rowloc;
                const uint2 mw = mwv[mt * 2 + rh];
                const bool hi = (l - kt) >= 96;
                const bool lo = (kt - l) >= 33;
                float rsum = 0.f;
                #pragma unroll
                for (int j = 0; j < 8; j++) {
                    const int k0 = 8 * j + 2 * lc;
                    float v0 = sacc[mt][j][rh * 2 + 0];
                    float v1 = sacc[mt][j][rh * 2 + 1];
                    float b0v, b1v;
                    if (hi)      { b0v = rel64c; b1v = rel64c; }
                    else if (lo) { b0v = rel0c;  b1v = rel0c;  }
                    else {
                        int e = l - kt - k0 + 32;
                        int e0 = e < 0 ? 0 : (e > 64 ? 64 : e);
                        int e1 = e - 1; e1 = e1 < 0 ? 0 : (e1 > 64 ? 64 : e1);
                        b0v = srel[e0]; b1v = srel[e1];
                    }
                    unsigned mword = (j < 4) ? mw.x : mw.y;
                    float p0 = ((mword >> (k0 & 31)) & 1u)       ? __expf(fmaf(v0, 0.125f, b0v)) : 0.f;
                    float p1 = ((mword >> ((k0 + 1) & 31)) & 1u) ? __expf(fmaf(v1, 0.125f, b1v)) : 0.f;
                    rsum += p0 + p1;
                    uint2 pp; pp.x = tf32b(p0); pp.y = tf32b(p1);
                    *(uint2*)(Pw + rowloc * 68 + k0) = pp;
                }
                rsum += __shfl_xor_sync(0xffffffffu, rsum, 1);
                rsum += __shfl_xor_sync(0xffffffffu, rsum, 2);
                lsum4[mt * 2 + rh] += rsum;
            }
        }
        __syncwarp();

        #pragma unroll
        for (int ks = 0; ks < 8; ks++) {
            uint32_t af[2][4];
            #pragma unroll
            for (int mt = 0; mt < 2; mt++) {
                const uint32_t* pb = (const uint32_t*)(Pw + (mt * 16 + lr) * 68 + ks * 8 + lc);
                af[mt][0] = pb[0];
                af[mt][1] = pb[8 * 68];
                af[mt][2] = pb[4];
                af[mt][3] = pb[8 * 68 + 4];
            }
            #pragma unroll
            for (int j = 0; j < 8; j++) {
                const float* vb = Vs + (ks * 8 + lc) * 68 + 8 * j + lr;
                uint32_t b0 = tf32b(vb[0]);
                uint32_t b1 = tf32b(vb[4 * 68]);
                mma8(oacc[0][j], af[0], b0, b1);
                mma8(oacc[1][j], af[1], b0, b1);
            }
        }
        __syncwarp();
    }

    #pragma unroll
    for (int mt = 0; mt < 2; mt++) {
        #pragma unroll
        for (int rh = 0; rh < 2; rh++) {
            const int rowloc = mt * 16 + rh * 8 + lr;
            const float inv = 1.f / lsum4[mt * 2 + rh];
            #pragma unroll
            for (int j = 0; j < 8; j++) {
                float2 o;
                o.x = oacc[mt][j][rh * 2 + 0] * inv;
                o.y = oacc[mt][j][rh * 2 + 1] * inv;
                *(float2*)(Pw + rowloc * 68 + 8 * j + 2 * lc) = o;
            }
        }
    }
    __syncwarp();
    {
        const int l = q0 + wq + lane;
        float* ob = g_att + ((size_t)b * CC + h * 64) * LL + l;
        #pragma unroll
        for (int dd = 0; dd < 64; dd++)
            ob[(size_t)dd * LL] = Pw[lane * 68 + dd];
    }
}

// ======================= tf32 mma GEMMs (3-term split) ======================
// SMEM float offsets for mma GEMM kernels
#define XS_STRIDE 264
#define WS_STRIDE 68
#define G_XS 0                       // 64 x 264 = 16896 floats
#define G_WH 16896                   // 64 x 68  = 4352
#define G_WL (16896 + 4352)          // 4352
#define G_TOTF (16896 + 8704)        // 25600 floats
#define G_BYTES (G_TOTF * 4)         // 102400 bytes

// out[b,h,l,d] = sum_c (x[b,c,l]+pos[c,l]) * W[h*64+d, c] + bias
// CTA: 256 rows (l) x 64 cols (one head), K=512 in chunks of 64.
__global__ __launch_bounds__(256) void gemm_qkv_mma(
    const float* __restrict__ x, const float* __restrict__ pos,
    const float* __restrict__ Wq, const float* __restrict__ bq,
    const float* __restrict__ Wk, const float* __restrict__ bk,
    const float* __restrict__ Wv, const float* __restrict__ bv)
{
    extern __shared__ float sm[];
    const int tid = threadIdx.x, wid = tid >> 5, lane = tid & 31;
    const int lr = lane >> 2, lc = lane & 3;
    const int l0 = blockIdx.x * 256;
    const int h = blockIdx.y;
    const int zz = blockIdx.z;
    const int b = zz / 3, proj = zz % 3;
    const float* W    = (proj == 0) ? Wq : (proj == 1) ? Wk : Wv;
    const float* bias = (proj == 0) ? bq : (proj == 1) ? bk : bv;
    float* out        = (proj == 0) ? g_q : (proj == 1) ? g_k : g_v;
    const int oc0 = h * 64;

    float acc[2][8][4] = {};

    for (int kt = 0; kt < CC; kt += 64) {
        __syncthreads();
        // X chunk: 64 c-rows x 256 l-cols (x + pos)
        #pragma unroll
        for (int i = 0; i < 16; i++) {
            int fidx = i * 256 + tid;
            int c = fidx >> 6, l4 = (fidx & 63) * 4;
            float4 xv = *(const float4*)(x   + ((size_t)(b * CC + kt + c)) * LL + l0 + l4);
            float4 pv = *(const float4*)(pos + ((size_t)(kt + c)) * LL + l0 + l4);
            float4 s = make_float4(xv.x + pv.x, xv.y + pv.y, xv.z + pv.z, xv.w + pv.w);
            *(float4*)(sm + G_XS + c * XS_STRIDE + l4) = s;
        }
        // W chunk: 64 oc-rows x 64 c-cols, pre-split hi/lo (tf32 bits)
        #pragma unroll
        for (int i = 0; i < 4; i++) {
            int fidx = i * 256 + tid;
            int oc = fidx >> 4, c4 = (fidx & 15) * 4;
            float4 wv = *(const float4*)(W + (size_t)(oc0 + oc) * CC + kt + c4);
            uint4 hi, lo;
            hi.x = tf32b(wv.x); lo.x = tf32b(wv.x - __uint_as_float(hi.x));
            hi.y = tf32b(wv.y); lo.y = tf32b(wv.y - __uint_as_float(hi.y));
            hi.z = tf32b(wv.z); lo.z = tf32b(wv.z - __uint_as_float(hi.z));
            hi.w = tf32b(wv.w); lo.w = tf32b(wv.w - __uint_as_float(hi.w));
            *(uint4*)(sm + G_WH + oc * WS_STRIDE + c4) = hi;
            *(uint4*)(sm + G_WL + oc * WS_STRIDE + c4) = lo;
        }
        __syncthreads();

        const float* Xs = sm + G_XS;
        const uint32_t* Wh = (const uint32_t*)(sm + G_WH);
        const uint32_t* Wl = (const uint32_t*)(sm + G_WL);
        #pragma unroll
        for (int ks = 0; ks < 8; ks++) {
            uint32_t ahi[2][4], alo[2][4];
            #pragma unroll
            for (int mt = 0; mt < 2; mt++) {
                const float* ab = Xs + (ks * 8 + lc) * XS_STRIDE + wid * 32 + mt * 16 + lr;
                float a0 = ab[0], a1 = ab[8], a2 = ab[4 * XS_STRIDE], a3 = ab[4 * XS_STRIDE + 8];
                ahi[mt][0] = tf32b(a0); alo[mt][0] = tf32b(a0 - __uint_as_float(ahi[mt][0]));
                ahi[mt][1] = tf32b(a1); alo[mt][1] = tf32b(a1 - __uint_as_float(ahi[mt][1]));
                ahi[mt][2] = tf32b(a2); alo[mt][2] = tf32b(a2 - __uint_as_float(ahi[mt][2]));
                ahi[mt][3] = tf32b(a3); alo[mt][3] = tf32b(a3 - __uint_as_float(ahi[mt][3]));
            }
            #pragma unroll
            for (int j = 0; j < 8; j++) {
                const uint32_t* wb  = Wh + (8 * j + lr) * WS_STRIDE + ks * 8 + lc;
                const uint32_t* wlb = Wl + (8 * j + lr) * WS_STRIDE + ks * 8 + lc;
                uint32_t bh0 = wb[0], bh1 = wb[4];
                uint32_t bl0 = wlb[0], bl1 = wlb[4];
                mma8(acc[0][j], ahi[0], bh0, bh1);
                mma8(acc[1][j], ahi[1], bh0, bh1);
                mma8(acc[0][j], alo[0], bh0, bh1);
                mma8(acc[1][j], alo[1], bh0, bh1);
                mma8(acc[0][j], ahi[0], bl0, bl1);
                mma8(acc[1][j], ahi[1], bl0, bl1);
            }
        }
    }

    // epilogue: + bias, store (l, d) row-major per (b,h)
    #pragma unroll
    for (int j = 0; j < 8; j++) {
        float2 bv2 = *(const float2*)(bias + oc0 + 8 * j + 2 * lc);
        #pragma unroll
        for (int mt = 0; mt < 2; mt++) {
            int l = l0 + wid * 32 + mt * 16 + lr;
            size_t rb = ((size_t)(b * NH + h) * LL + l) * HD + 8 * j + 2 * lc;
            float2 r0 = make_float2(acc[mt][j][0] + bv2.x, acc[mt][j][1] + bv2.y);
            float2 r1 = make_float2(acc[mt][j][2] + bv2.x, acc[mt][j][3] + bv2.y);
            *(float2*)(out + rb) = r0;
            *(float2*)(out + rb + (size_t)8 * HD) = r1;
        }
    }
}

// y[b,oc,l] = sum_c Wo[oc,c]*att[b,c,l] + bo[oc] + x[b,oc,l]
__global__ __launch_bounds__(256) void gemm_proj_mma(
    const float* __restrict__ W, const float* __restrict__ bias,
    const float* __restrict__ xres)
{
    extern __shared__ float sm[];
    const int tid = threadIdx.x, wid = tid >> 5, lane = tid & 31;
    const int lr = lane >> 2, lc = lane & 3;
    const int l0 = blockIdx.x * 256;
    const int oc0 = blockIdx.y * 64;
    const int b = blockIdx.z;

    float acc[2][8][4] = {};

    for (int kt = 0; kt < CC; kt += 64) {
        __syncthreads();
        #pragma unroll
        for (int i = 0; i < 16; i++) {
            int fidx = i * 256 + tid;
            int c = fidx >> 6, l4 = (fidx & 63) * 4;
            float4 s = *(const float4*)(g_att + ((size_t)(b * CC + kt + c)) * LL + l0 + l4);
            *(float4*)(sm + G_XS + c * XS_STRIDE + l4) = s;
        }
        #pragma unroll
        for (int i = 0; i < 4; i++) {
            int fidx = i * 256 + tid;
            int oc = fidx >> 4, c4 = (fidx & 15) * 4;
            float4 wv = *(const float4*)(W + (size_t)(oc0 + oc) * CC + kt + c4);
            uint4 hi, lo;
            hi.x = tf32b(wv.x); lo.x = tf32b(wv.x - __uint_as_float(hi.x));
            hi.y = tf32b(wv.y); lo.y = tf32b(wv.y - __uint_as_float(hi.y));
            hi.z = tf32b(wv.z); lo.z = tf32b(wv.z - __uint_as_float(hi.z));
            hi.w = tf32b(wv.w); lo.w = tf32b(wv.w - __uint_as_float(hi.w));
            *(uint4*)(sm + G_WH + oc * WS_STRIDE + c4) = hi;
            *(uint4*)(sm + G_WL + oc * WS_STRIDE + c4) = lo;
        }
        __syncthreads();

        const float* Xs = sm + G_XS;
        const uint32_t* Wh = (const uint32_t*)(sm + G_WH);
        const uint32_t* Wl = (const uint32_t*)(sm + G_WL);
        #pragma unroll
        for (int ks = 0; ks < 8; ks++) {
            uint32_t ahi[2][4], alo[2][4];
            #pragma unroll
            for (int mt = 0; mt < 2; mt++) {
                const float* ab = Xs + (ks * 8 + lc) * XS_STRIDE + wid * 32 + mt * 16 + lr;
                float a0 = ab[0], a1 = ab[8], a2 = ab[4 * XS_STRIDE], a3 = ab[4 * XS_STRIDE + 8];
                ahi[mt][0] = tf32b(a0); alo[mt][0] = tf32b(a0 - __uint_as_float(ahi[mt][0]));
                ahi[mt][1] = tf32b(a1); alo[mt][1] = tf32b(a1 - __uint_as_float(ahi[mt][1]));
                ahi[mt][2] = tf32b(a2); alo[mt][2] = tf32b(a2 - __uint_as_float(ahi[mt][2]));
                ahi[mt][3] = tf32b(a3); alo[mt][3] = tf32b(a3 - __uint_as_float(ahi[mt][3]));
            }
            #pragma unroll
            for (int j = 0; j < 8; j++) {
                const uint32_t* wb  = Wh + (8 * j + lr) * WS_STRIDE + ks * 8 + lc;
                const uint32_t* wlb = Wl + (8 * j + lr) * WS_STRIDE + ks * 8 + lc;
                uint32_t bh0 = wb[0], bh1 = wb[4];
                uint32_t bl0 = wlb[0], bl1 = wlb[4];
                mma8(acc[0][j], ahi[0], bh0, bh1);
                mma8(acc[1][j], ahi[1], bh0, bh1);
                mma8(acc[0][j], alo[0], bh0, bh1);
                mma8(acc[1][j], alo[1], bh0, bh1);
                mma8(acc[0][j], ahi[0], bl0, bl1);
                mma8(acc[1][j], ahi[1], bl0, bl1);
            }
        }
    }

    // transpose via per-warp smem, then coalesced (oc, l) store + bias + residual
    __syncthreads();
    float* Pw = sm + G_XS + wid * (32 * 66);
    #pragma unroll
    for (int j = 0; j < 8; j++) {
        #pragma unroll
        for (int mt = 0; mt < 2; mt++) {
            int r0 = mt * 16 + lr;
            *(float2*)(Pw + r0 * 66 + 8 * j + 2 * lc) = make_float2(acc[mt][j][0], acc[mt][j][1]);
            *(float2*)(Pw + (r0 + 8) * 66 + 8 * j + 2 * lc) = make_float2(acc[mt][j][2], acc[mt][j][3]);
        }
    }
    __syncwarp();
    {
        const int l = l0 + wid * 32 + lane;
        #pragma unroll 8
        for (int dd = 0; dd < 64; dd++) {
            int oc = oc0 + dd;
            size_t gidx = ((size_t)(b * CC + oc)) * LL + l;
            float val = Pw[lane * 66 + dd] + bias[oc] + xres[gidx];
            g_y[gidx] = val;
        }
    }
}

// ---------------------------------------------------------------------------
// LayerNorm: 32 pixels x 512 channels per CTA, coalesced over l.
// ---------------------------------------------------------------------------
__global__ __launch_bounds__(256) void ln_kernel(
    const float* __restrict__ gamma, const float* __restrict__ beta,
    float* __restrict__ out)
{
    const int w = threadIdx.x >> 5, lane = threadIdx.x & 31;
    const int p0 = blockIdx.x * 32;                 // LL % 32 == 0, so one b per block
    const int b = p0 / LL;
    const int l = p0 % LL + lane;
    const float* yb = g_y + (size_t)b * CC * LL;

    float vals[64];
    float s = 0.f, s2 = 0.f;
    #pragma unroll
    for (int i = 0; i < 64; i++) {
        float v = yb[(size_t)(w * 64 + i) * LL + l];
        vals[i] = v; s += v; s2 += v * v;
    }
    __shared__ float ss[8][32], ss2[8][32];
    ss[w][lane] = s; ss2[w][lane] = s2;
    __syncthreads();
    float st = 0.f, st2 = 0.f;
    #pragma unroll
    for (int i = 0; i < 8; i++) { st += ss[i][lane]; st2 += ss2[i][lane]; }
    float mean = st * (1.f / CC);
    float var = st2 * (1.f / CC) - mean * mean;
    float rs = rsqrtf(var + 1e-5f);

    float* ob = out + (size_t)b * CC * LL;
    #pragma unroll
    for (int i = 0; i < 64; i++) {
        int c = w * 64 + i;
        ob[(size_t)c * LL + l] = (vals[i] - mean) * rs * gamma[c] + beta[c];
    }
}

// ---------------------------------------------------------------------------
extern "C" void kernel_launch(void* const* d_in, const int* in_sizes, int n_in,
                              void* d_out, int out_size)
{
    const float* x    = (const float*)d_in[0];
    const int*   mask = (const int*)d_in[1];
    const float* pos  = (const float*)d_in[2];
    const float* Wq = (const float*)d_in[3];
    const float* bq = (const float*)d_in[4];
    const float* Wk = (const float*)d_in[5];
    const float* bk = (const float*)d_in[6];
    const float* Wv = (const float*)d_in[7];
    const float* bv = (const float*)d_in[8];
    const float* Wo = (const float*)d_in[9];
    const float* bo = (const float*)d_in[10];
    const float* rel = (const float*)d_in[11];
    const float* gam = (const float*)d_in[12];
    const float* bet = (const float*)d_in[13];
    float* out = (float*)d_out;

    static bool attr_set = false;
    if (!attr_set) {
        cudaFuncSetAttribute(attn_kernel, cudaFuncAttributeMaxDynamicSharedMemorySize, SM_BYTES);
        cudaFuncSetAttribute(gemm_qkv_mma, cudaFuncAttributeMaxDynamicSharedMemorySize, G_BYTES);
        cudaFuncSetAttribute(gemm_proj_mma, cudaFuncAttributeMaxDynamicSharedMemorySize, G_BYTES);
        attr_set = true;
    }

    gemm_qkv_mma<<<dim3(LL / 256, NH, BB * 3), 256, G_BYTES>>>(x, pos, Wq, bq, Wk, bk, Wv, bv);
    pack_kernel<<<(NH * LL * MW) / 256, 256>>>(mask);
    attn_kernel<<<dim3(LL / 256, NH, BB), 256, SM_BYTES>>>(rel);
    gemm_proj_mma<<<dim3(LL / 256, CC / 64, BB), 256, G_BYTES>>>(Wo, bo, x);
    ln_kernel<<<(BB * LL) / 32, 256>>>(gam, bet, out);
}